// round 1
// baseline (speedup 1.0000x reference)
#include <cuda_runtime.h>
#include <math.h>

// Problem constants (match reference)
#define FF       20
#define V_FIELD  5000
#define TOTALV   (FF * V_FIELD)     // 100000
#define DD       64
#define BB       8192
#define NPAIRS   190

// Schedule: 10 groups of 19 pairs. Group is the SLOW grid axis so concurrent
// CTAs share the same ~49MB L2 working set (19 pairs x 2 x 1.28MB regions).
#define PPG              19
#define NGROUPS          10
#define WARPS_PER_BLOCK  8
#define WS               2                       // samples per warp
#define SAMPLES_PER_BLOCK (WARPS_PER_BLOCK * WS) // 16
#define NCHUNKS          (BB / SAMPLES_PER_BLOCK) // 512

// Per-sample interaction accumulator (scratch; no cudaMalloc allowed).
__device__ float g_acc[BB];

// Main gather/dot kernel: grid = (chunk, group). Each warp owns WS samples;
// for each it loops the group's 19 pairs, each pair = two coalesced 256B row
// loads (float2 per lane) + 2 FMAs per lane; one warp reduction + one
// atomicAdd per (sample, group).
__global__ void __launch_bounds__(WARPS_PER_BLOCK * 32)
ffm_pairs(const int* __restrict__ x, const float* __restrict__ W) {
    __shared__ int sI[PPG], sJ[PPG];
    const int g = blockIdx.y;
    if (threadIdx.x < PPG) {
        int p = g * PPG + threadIdx.x;
        int i = 0, rem = p;
        while (rem >= FF - 1 - i) { rem -= FF - 1 - i; i++; }
        sI[threadIdx.x] = i;
        sJ[threadIdx.x] = i + 1 + rem;
    }
    __syncthreads();

    const int lane = threadIdx.x & 31;
    const int w    = threadIdx.x >> 5;
    const int sbase = blockIdx.x * SAMPLES_PER_BLOCK + w * WS;
    const float2* __restrict__ W2 = (const float2*)W;

    for (int ss = 0; ss < WS; ss++) {
        const int s = sbase + ss;
        // Preload this sample's full index row across lanes (broadcast via shfl).
        int xv = 0;
        if (lane < FF) xv = x[s * FF + lane];

        float acc = 0.f;
        #pragma unroll
        for (int q = 0; q < PPG; q++) {
            const int i = sI[q];
            const int j = sJ[q];
            const int xi = __shfl_sync(0xffffffffu, xv, i);
            const int xj = __shfl_sync(0xffffffffu, xv, j);
            // a = W[j, i*V_FIELD + xi, :], b = W[i, j*V_FIELD + xj, :]
            const size_t ra = ((size_t)j * TOTALV + (size_t)(i * V_FIELD + xi)) * (DD / 2);
            const size_t rb = ((size_t)i * TOTALV + (size_t)(j * V_FIELD + xj)) * (DD / 2);
            const float2 av = __ldg(&W2[ra + lane]);
            const float2 bv = __ldg(&W2[rb + lane]);
            acc = fmaf(av.x, bv.x, acc);
            acc = fmaf(av.y, bv.y, acc);
        }
        #pragma unroll
        for (int o = 16; o; o >>= 1)
            acc += __shfl_xor_sync(0xffffffffu, acc, o);
        if (lane == 0)
            atomicAdd(&g_acc[s], acc);
    }
}

// Finalize: linear term gather + bias + sigmoid.
__global__ void ffm_final(const int* __restrict__ x, const float* __restrict__ Wl,
                          const float* __restrict__ bias, float* __restrict__ out) {
    const int s = blockIdx.x * blockDim.x + threadIdx.x;
    if (s >= BB) return;
    float lin = 0.f;
    #pragma unroll
    for (int f = 0; f < FF; f++) {
        const int v = x[s * FF + f];
        lin += __ldg(&Wl[f * V_FIELD + v]);
    }
    const float z = lin + bias[0] + g_acc[s];
    out[s] = 1.f / (1.f + __expf(-z));
}

extern "C" void kernel_launch(void* const* d_in, const int* in_sizes, int n_in,
                              void* d_out, int out_size) {
    const int*   x    = (const int*)d_in[0];
    const float* W    = (const float*)d_in[1];
    const float* Wl   = (const float*)d_in[2];
    const float* bias = (const float*)d_in[3];
    float*       out  = (float*)d_out;

    void* accptr = nullptr;
    cudaGetSymbolAddress(&accptr, g_acc);
    cudaMemsetAsync(accptr, 0, BB * sizeof(float), 0);

    dim3 grid(NCHUNKS, NGROUPS);
    ffm_pairs<<<grid, WARPS_PER_BLOCK * 32>>>(x, W);
    ffm_final<<<(BB + 255) / 256, 256>>>(x, Wl, bias, out);
}

// round 2
// speedup vs baseline: 1.2677x; 1.2677x over previous
#include <cuda_runtime.h>
#include <math.h>

// Problem constants (match reference)
#define FF       20
#define V_FIELD  5000
#define TOTALV   (FF * V_FIELD)     // 100000
#define DD       64
#define BB       8192
#define NPAIRS   190

// Schedule: 10 groups of 19 pairs. Group is the SLOW grid axis so concurrent
// CTAs share the same ~49MB L2 working set (19 pairs x 2 x 1.28MB regions).
#define PPG              19
#define NGROUPS          10
#define WARPS_PER_BLOCK  8
#define WS               2                       // samples per warp
#define SAMPLES_PER_BLOCK (WARPS_PER_BLOCK * WS) // 16
#define NCHUNKS          (BB / SAMPLES_PER_BLOCK) // 512

// Per-(group, sample) partial interaction sums. Plain stores, no atomics,
// no memset needed (every slot is written every launch -> deterministic).
__device__ float g_part[NGROUPS * BB];

// Main gather/dot kernel: grid = (chunk, group). Each warp owns WS samples;
// for each it loops the group's 19 pairs, each pair = two coalesced 256B row
// loads (float2 per lane) + 2 FMAs per lane; one warp reduction + one plain
// store per (sample, group).
__global__ void __launch_bounds__(WARPS_PER_BLOCK * 32)
ffm_pairs(const int* __restrict__ x, const float* __restrict__ W) {
    __shared__ int sI[PPG], sJ[PPG];
    const int g = blockIdx.y;
    if (threadIdx.x < PPG) {
        int p = g * PPG + threadIdx.x;
        int i = 0, rem = p;
        while (rem >= FF - 1 - i) { rem -= FF - 1 - i; i++; }
        sI[threadIdx.x] = i;
        sJ[threadIdx.x] = i + 1 + rem;
    }
    __syncthreads();

    const int lane = threadIdx.x & 31;
    const int w    = threadIdx.x >> 5;
    const int sbase = blockIdx.x * SAMPLES_PER_BLOCK + w * WS;
    const float2* __restrict__ W2 = (const float2*)W;

    for (int ss = 0; ss < WS; ss++) {
        const int s = sbase + ss;
        // Preload this sample's full index row across lanes (broadcast via shfl).
        int xv = 0;
        if (lane < FF) xv = x[s * FF + lane];

        float acc = 0.f;
        #pragma unroll
        for (int q = 0; q < PPG; q++) {
            const int i = sI[q];
            const int j = sJ[q];
            const int xi = __shfl_sync(0xffffffffu, xv, i);
            const int xj = __shfl_sync(0xffffffffu, xv, j);
            // a = W[j, i*V_FIELD + xi, :], b = W[i, j*V_FIELD + xj, :]
            const size_t ra = ((size_t)j * TOTALV + (size_t)(i * V_FIELD + xi)) * (DD / 2);
            const size_t rb = ((size_t)i * TOTALV + (size_t)(j * V_FIELD + xj)) * (DD / 2);
            const float2 av = __ldg(&W2[ra + lane]);
            const float2 bv = __ldg(&W2[rb + lane]);
            acc = fmaf(av.x, bv.x, acc);
            acc = fmaf(av.y, bv.y, acc);
        }
        #pragma unroll
        for (int o = 16; o; o >>= 1)
            acc += __shfl_xor_sync(0xffffffffu, acc, o);
        if (lane == 0)
            g_part[g * BB + s] = acc;
    }
}

// Finalize: warp-per-sample. Lanes 0-19 gather the linear term, lanes 0-9
// concurrently pick up the 10 group partials, single butterfly reduction,
// lane 0 applies bias + sigmoid. 8192 warps -> high occupancy, 30-way MLP.
__global__ void __launch_bounds__(256)
ffm_final(const int* __restrict__ x, const float* __restrict__ Wl,
          const float* __restrict__ bias, float* __restrict__ out) {
    const int warp = (blockIdx.x * blockDim.x + threadIdx.x) >> 5;
    const int lane = threadIdx.x & 31;
    if (warp >= BB) return;
    const int s = warp;

    float v = 0.f;
    if (lane < FF) {
        const int xv = x[s * FF + lane];
        v = __ldg(&Wl[lane * V_FIELD + xv]);
    }
    if (lane < NGROUPS) {
        v += g_part[lane * BB + s];
    }
    #pragma unroll
    for (int o = 16; o; o >>= 1)
        v += __shfl_xor_sync(0xffffffffu, v, o);
    if (lane == 0) {
        const float z = v + bias[0];
        out[s] = 1.f / (1.f + __expf(-z));
    }
}

extern "C" void kernel_launch(void* const* d_in, const int* in_sizes, int n_in,
                              void* d_out, int out_size) {
    const int*   x    = (const int*)d_in[0];
    const float* W    = (const float*)d_in[1];
    const float* Wl   = (const float*)d_in[2];
    const float* bias = (const float*)d_in[3];
    float*       out  = (float*)d_out;

    dim3 grid(NCHUNKS, NGROUPS);
    ffm_pairs<<<grid, WARPS_PER_BLOCK * 32>>>(x, W);
    // 8192 warps = 8192*32 threads / 256 per block
    ffm_final<<<(BB * 32) / 256, 256>>>(x, Wl, bias, out);
}